// round 5
// baseline (speedup 1.0000x reference)
#include <cuda_runtime.h>
#include <cuda_bf16.h>
#include <math.h>

#define SEQL   2048
#define BATCH  2
#define DMODEL 1024
#define NHEADS 16
#define DHEAD  64
#define MR     (BATCH * SEQL)   // 4096 rows
#define NSEG   16
#define SEGROWS (SEQL / NSEG)   // 128
#define KP     (DMODEL / 2)     // 512 bf16-pair columns

// ---------------- scratch ----------------
__device__ float    g_Q[(size_t)MR * DMODEL];          // f32 (LN'd)
__device__ float    g_K[(size_t)MR * DMODEL];
__device__ float    g_V[(size_t)MR * DMODEL];
__device__ unsigned g_Qt[(size_t)MR * DMODEL];         // tf32 hi bits (full width, for attn)
__device__ unsigned g_Kt[(size_t)MR * DMODEL];
__device__ uint2    g_Xt[(size_t)MR * DMODEL];         // tf32 hi/lo interleaved
__device__ uint2    g_Wqkt[(size_t)2 * DMODEL * DMODEL];
__device__ uint2    g_Qhl[(size_t)MR * DHEAD];         // head-0 LN'd hi/lo
__device__ uint2    g_Khl[(size_t)MR * DHEAD];
__device__ unsigned g_Xh[(size_t)MR * KP];             // bf16 pair splits
__device__ unsigned g_Xl[(size_t)MR * KP];
__device__ unsigned g_Wvh[(size_t)DMODEL * KP];
__device__ unsigned g_Wvl[(size_t)DMODEL * KP];
__device__ unsigned g_Woh[(size_t)DMODEL * KP];
__device__ unsigned g_Wol[(size_t)DMODEL * KP];
__device__ unsigned g_Vth[(size_t)BATCH * NHEADS * DHEAD * (SEQL / 2)];  // [bh][d][n-pairs]
__device__ unsigned g_Vtl[(size_t)BATCH * NHEADS * DHEAD * (SEQL / 2)];
__device__ unsigned g_Oh[(size_t)MR * KP];
__device__ unsigned g_Ol[(size_t)MR * KP];
__device__ float    g_F[(size_t)BATCH * SEQL * SEQL];
__device__ float    g_P[(size_t)BATCH * NSEG * SEQL];

// ---------------- helpers ----------------
__device__ __forceinline__ unsigned f2t(float x) {
    unsigned r;
    asm("cvt.rna.tf32.f32 %0, %1;" : "=r"(r) : "f"(x));
    return r;
}

__device__ __forceinline__ void bsplit(float x0, float x1, unsigned& h, unsigned& l) {
    asm("cvt.rn.bf16x2.f32 %0, %1, %2;" : "=r"(h) : "f"(x1), "f"(x0));
    __nv_bfloat162 hb = *reinterpret_cast<__nv_bfloat162*>(&h);
    float2 hf = __bfloat1622float2(hb);
    float r0 = x0 - hf.x, r1 = x1 - hf.y;
    asm("cvt.rn.bf16x2.f32 %0, %1, %2;" : "=r"(l) : "f"(r1), "f"(r0));
}

__device__ __forceinline__ uint2 tsplit1(float x) {
    unsigned h = f2t(x);
    unsigned l = f2t(x - __uint_as_float(h));
    return make_uint2(h, l);
}

#define MMA(C, A0, A1, A2, A3, B0, B1)                                         \
    asm volatile(                                                              \
        "mma.sync.aligned.m16n8k8.row.col.f32.tf32.tf32.f32 "                  \
        "{%0,%1,%2,%3},{%4,%5,%6,%7},{%8,%9},{%0,%1,%2,%3};"                   \
        : "+f"((C)[0]), "+f"((C)[1]), "+f"((C)[2]), "+f"((C)[3])               \
        : "r"(A0), "r"(A1), "r"(A2), "r"(A3), "r"(B0), "r"(B1))

#define MMAB(C, A0, A1, A2, A3, B0, B1)                                        \
    asm volatile(                                                              \
        "mma.sync.aligned.m16n8k16.row.col.f32.bf16.bf16.f32 "                 \
        "{%0,%1,%2,%3},{%4,%5,%6,%7},{%8,%9},{%0,%1,%2,%3};"                   \
        : "+f"((C)[0]), "+f"((C)[1]), "+f"((C)[2]), "+f"((C)[3])               \
        : "r"(A0), "r"(A1), "r"(A2), "r"(A3), "r"(B0), "r"(B1))

// 3xTF32 product accumulate: hi*hi + hi*lo + lo*hi
#define MMA3(C, a0, a1, a2, a3, b0, b1)                                        \
    do {                                                                       \
        MMA(C, (a0).x, (a1).x, (a2).x, (a3).x, (b0).x, (b1).x);                \
        MMA(C, (a0).x, (a1).x, (a2).x, (a3).x, (b0).y, (b1).y);                \
        MMA(C, (a0).y, (a1).y, (a2).y, (a3).y, (b0).x, (b1).x);                \
    } while (0)

// ---------------- elementwise split kernels ----------------
__global__ __launch_bounds__(256) void tsplit(const float* __restrict__ src,
                                              uint2* __restrict__ dst, int n) {
    int i = blockIdx.x * 256 + threadIdx.x;
    if (i < n) dst[i] = tsplit1(src[i]);
}

__global__ __launch_bounds__(256) void split_pairs(const float* __restrict__ src,
                                                   unsigned* __restrict__ h,
                                                   unsigned* __restrict__ l, int npairs) {
    int i = blockIdx.x * 256 + threadIdx.x;
    if (i < npairs) {
        float2 v = ((const float2*)src)[i];
        unsigned hh, ll;
        bsplit(v.x, v.y, hh, ll);
        h[i] = hh;
        l[i] = ll;
    }
}

// ---------------- fused QK projection: tf32x3, pure LDS+MMA mainloop --------------
// A = Xt (M x K uint2), B = Wqkt (2048 x K uint2). Tile 128x128, BK=16.
// Output column n<1024 -> g_Q, else g_K.
__global__ __launch_bounds__(256) void gemm_t3(const uint2* __restrict__ Ahl,
                                               const uint2* __restrict__ Bhl,
                                               float* __restrict__ Y0,
                                               float* __restrict__ Y1,
                                               int M, int Nhalf, int K) {
    __shared__ uint2 sA[128 * 20];
    __shared__ uint2 sB[128 * 20];
    const int tid = threadIdx.x, lane = tid & 31, warp = tid >> 5;
    const int g = lane >> 2, tg = lane & 3;
    const int wm = warp >> 2, wn = warp & 3;
    const int m0 = blockIdx.y * 128, n0 = blockIdx.x * 128;

    float c[4][4][4] = {};

    for (int k0 = 0; k0 < K; k0 += 16) {
#pragma unroll
        for (int t = 0; t < 4; t++) {
            int idx = tid + t * 256;             // 0..1023 uint4 slots
            int r = idx >> 3, c2 = (idx & 7) * 2;
            *(uint4*)&sA[r * 20 + c2] = *(const uint4*)&Ahl[(size_t)(m0 + r) * K + k0 + c2];
            *(uint4*)&sB[r * 20 + c2] = *(const uint4*)&Bhl[(size_t)(n0 + r) * K + k0 + c2];
        }
        __syncthreads();
#pragma unroll
        for (int kc = 0; kc < 2; kc++) {
            uint2 bf[4][2];
#pragma unroll
            for (int ni = 0; ni < 4; ni++) {
                int nb = (wn * 32 + ni * 8 + g) * 20 + kc * 8 + tg;
                bf[ni][0] = sB[nb];
                bf[ni][1] = sB[nb + 4];
            }
#pragma unroll
            for (int mi = 0; mi < 4; mi++) {
                int r1 = (wm * 64 + mi * 16 + g) * 20 + kc * 8 + tg;
                int r2 = r1 + 8 * 20;
                uint2 a0 = sA[r1], a1 = sA[r2], a2 = sA[r1 + 4], a3 = sA[r2 + 4];
#pragma unroll
                for (int ni = 0; ni < 4; ni++)
                    MMA3(c[mi][ni], a0, a1, a2, a3, bf[ni][0], bf[ni][1]);
            }
        }
        __syncthreads();
    }

    float* Y = (n0 < Nhalf) ? Y0 : Y1;
    const int col0 = (n0 < Nhalf) ? n0 : n0 - Nhalf;
#pragma unroll
    for (int mi = 0; mi < 4; mi++)
#pragma unroll
        for (int ni = 0; ni < 4; ni++) {
            int r = m0 + wm * 64 + mi * 16 + g;
            int col = col0 + wn * 32 + ni * 8 + 2 * tg;
            *(float2*)&Y[(size_t)r * Nhalf + col] = make_float2(c[mi][ni][0], c[mi][ni][1]);
            *(float2*)&Y[(size_t)(r + 8) * Nhalf + col] = make_float2(c[mi][ni][2], c[mi][ni][3]);
        }
}

// ---------------- GEMM bf16 x3 (unchanged, already CVT-free) ----------------
__global__ __launch_bounds__(256) void gemm_bf3(const unsigned* __restrict__ Ah,
                                                const unsigned* __restrict__ Al,
                                                const unsigned* __restrict__ Bh,
                                                const unsigned* __restrict__ Bl,
                                                float* __restrict__ Y,
                                                int M, int N, int Kp) {
    __shared__ unsigned sAh[128 * 20], sAl[128 * 20];
    __shared__ unsigned sBh[128 * 20], sBl[128 * 20];
    const int tid = threadIdx.x, lane = tid & 31, warp = tid >> 5;
    const int g = lane >> 2, tg = lane & 3;
    const int wm = warp >> 2, wn = warp & 3;
    const int m0 = blockIdx.y * 128, n0 = blockIdx.x * 128;

    float c[4][4][4] = {};

    for (int k0 = 0; k0 < Kp; k0 += 16) {
#pragma unroll
        for (int t = 0; t < 2; t++) {
            int idx = tid + t * 256;
            int r = idx >> 2, c4 = (idx & 3) * 4;
            *(uint4*)&sAh[r * 20 + c4] = *(const uint4*)&Ah[(size_t)(m0 + r) * Kp + k0 + c4];
            *(uint4*)&sAl[r * 20 + c4] = *(const uint4*)&Al[(size_t)(m0 + r) * Kp + k0 + c4];
            *(uint4*)&sBh[r * 20 + c4] = *(const uint4*)&Bh[(size_t)(n0 + r) * Kp + k0 + c4];
            *(uint4*)&sBl[r * 20 + c4] = *(const uint4*)&Bl[(size_t)(n0 + r) * Kp + k0 + c4];
        }
        __syncthreads();
#pragma unroll
        for (int kc = 0; kc < 2; kc++) {
            unsigned bh[4][2], bl[4][2];
#pragma unroll
            for (int ni = 0; ni < 4; ni++) {
                int nb = (wn * 32 + ni * 8 + g) * 20 + kc * 8 + tg;
                bh[ni][0] = sBh[nb];
                bh[ni][1] = sBh[nb + 4];
                bl[ni][0] = sBl[nb];
                bl[ni][1] = sBl[nb + 4];
            }
#pragma unroll
            for (int mi = 0; mi < 4; mi++) {
                int r1 = (wm * 64 + mi * 16 + g) * 20 + kc * 8 + tg;
                int r2 = r1 + 8 * 20;
                unsigned ah0 = sAh[r1], ah1 = sAh[r2], ah2 = sAh[r1 + 4], ah3 = sAh[r2 + 4];
                unsigned al0 = sAl[r1], al1 = sAl[r2], al2 = sAl[r1 + 4], al3 = sAl[r2 + 4];
#pragma unroll
                for (int ni = 0; ni < 4; ni++) {
                    MMAB(c[mi][ni], ah0, ah1, ah2, ah3, bh[ni][0], bh[ni][1]);
                    MMAB(c[mi][ni], ah0, ah1, ah2, ah3, bl[ni][0], bl[ni][1]);
                    MMAB(c[mi][ni], al0, al1, al2, al3, bh[ni][0], bh[ni][1]);
                }
            }
        }
        __syncthreads();
    }

#pragma unroll
    for (int mi = 0; mi < 4; mi++)
#pragma unroll
        for (int ni = 0; ni < 4; ni++) {
            int r = m0 + wm * 64 + mi * 16 + g;
            int col = n0 + wn * 32 + ni * 8 + 2 * tg;
            *(float2*)&Y[(size_t)r * N + col] = make_float2(c[mi][ni][0], c[mi][ni][1]);
            *(float2*)&Y[(size_t)(r + 8) * N + col] = make_float2(c[mi][ni][2], c[mi][ni][3]);
        }
}

// ---------------- row LayerNorm + tf32 hi copy + head-0 hi/lo copy ----------------
__global__ __launch_bounds__(256) void ln_rows_t(float* __restrict__ Y,
                                                 const float* __restrict__ g,
                                                 const float* __restrict__ b,
                                                 unsigned* __restrict__ T,
                                                 uint2* __restrict__ HL) {
    const int row = blockIdx.x;
    float* y = Y + (size_t)row * DMODEL;
    unsigned* t = T + (size_t)row * DMODEL;
    __shared__ float red[256];

    float s = 0.f;
    for (int i = threadIdx.x; i < DMODEL; i += 256) s += y[i];
    red[threadIdx.x] = s;
    __syncthreads();
    for (int o = 128; o > 0; o >>= 1) {
        if (threadIdx.x < o) red[threadIdx.x] += red[threadIdx.x + o];
        __syncthreads();
    }
    const float mu = red[0] * (1.0f / DMODEL);
    __syncthreads();

    float v = 0.f;
    for (int i = threadIdx.x; i < DMODEL; i += 256) {
        float d = y[i] - mu;
        v += d * d;
    }
    red[threadIdx.x] = v;
    __syncthreads();
    for (int o = 128; o > 0; o >>= 1) {
        if (threadIdx.x < o) red[threadIdx.x] += red[threadIdx.x + o];
        __syncthreads();
    }
    const float rstd = rsqrtf(red[0] * (1.0f / DMODEL) + 1e-5f);
    __syncthreads();

    for (int i = threadIdx.x; i < DMODEL; i += 256) {
        float val = (y[i] - mu) * rstd * g[i] + b[i];
        y[i] = val;
        unsigned hi = f2t(val);
        t[i] = hi;
        if (i < DHEAD) {
            unsigned lo = f2t(val - __uint_as_float(hi));
            HL[(size_t)row * DHEAD + i] = make_uint2(hi, lo);
        }
    }
}

// ---------------- V transpose + bf16 split ----------------
__global__ __launch_bounds__(256) void vt_split() {
    __shared__ float tile[64][68];
    const int b = blockIdx.z, h = blockIdx.y, n0 = blockIdx.x * 64;
    const int tid = threadIdx.x;
#pragma unroll
    for (int t = 0; t < 4; t++) {
        int idx = tid + t * 256;
        int r = idx >> 4, c4 = (idx & 15) * 4;
        *(float4*)&tile[r][c4] =
            *(const float4*)&g_V[(size_t)(b * SEQL + n0 + r) * DMODEL + h * DHEAD + c4];
    }
    __syncthreads();
#pragma unroll
    for (int t = 0; t < 8; t++) {
        int idx = tid + t * 256;
        int d = idx >> 5, j = idx & 31;
        unsigned hh, ll;
        bsplit(tile[2 * j][d], tile[2 * j + 1][d], hh, ll);
        size_t off = ((size_t)((b * NHEADS + h) * DHEAD + d)) * (SEQL / 2) + (n0 >> 1) + j;
        g_Vth[off] = hh;
        g_Vtl[off] = ll;
    }
}

// ---------------- head-0 scores: tf32x3 pure LDS+MMA, BK=16, K=64 ----------------
__global__ __launch_bounds__(256) void head0_t3() {
    const int tid = threadIdx.x, lane = tid & 31, warp = tid >> 5;
    const int g = lane >> 2, tg = lane & 3;
    const int wm = warp >> 2, wn = warp & 3;
    const int bb = blockIdx.z;
    const int r0 = blockIdx.y * 128, mm0 = blockIdx.x * 128;

    // fully upper-triangle tile: C == 0 everywhere, skip MMAs
    if (mm0 >= r0 + 128) {
        const float2 z = make_float2(0.f, 0.f);
#pragma unroll
        for (int mi = 0; mi < 4; mi++)
#pragma unroll
            for (int ni = 0; ni < 4; ni++) {
                int r1 = r0 + wm * 64 + mi * 16 + g;
                int m = mm0 + wn * 32 + ni * 8 + 2 * tg;
                *(float2*)&g_F[(size_t)(bb * SEQL + r1) * SEQL + m] = z;
                *(float2*)&g_F[(size_t)(bb * SEQL + r1 + 8) * SEQL + m] = z;
            }
        return;
    }

    __shared__ uint2 sA[128 * 20];
    __shared__ uint2 sB[128 * 20];
    const uint2* Aq = g_Qhl + (size_t)(bb * SEQL + r0) * DHEAD;
    const uint2* Bk = g_Khl + (size_t)(bb * SEQL + mm0) * DHEAD;

    float c[4][4][4] = {};

    for (int k0 = 0; k0 < DHEAD; k0 += 16) {
#pragma unroll
        for (int t = 0; t < 4; t++) {
            int idx = tid + t * 256;
            int r = idx >> 3, c2 = (idx & 7) * 2;
            *(uint4*)&sA[r * 20 + c2] = *(const uint4*)&Aq[(size_t)r * DHEAD + k0 + c2];
            *(uint4*)&sB[r * 20 + c2] = *(const uint4*)&Bk[(size_t)r * DHEAD + k0 + c2];
        }
        __syncthreads();
#pragma unroll
        for (int kc = 0; kc < 2; kc++) {
            uint2 bf[4][2];
#pragma unroll
            for (int ni = 0; ni < 4; ni++) {
                int nb = (wn * 32 + ni * 8 + g) * 20 + kc * 8 + tg;
                bf[ni][0] = sB[nb];
                bf[ni][1] = sB[nb + 4];
            }
#pragma unroll
            for (int mi = 0; mi < 4; mi++) {
                int r1 = (wm * 64 + mi * 16 + g) * 20 + kc * 8 + tg;
                int r2 = r1 + 8 * 20;
                uint2 a0 = sA[r1], a1 = sA[r2], a2 = sA[r1 + 4], a3 = sA[r2 + 4];
#pragma unroll
                for (int ni = 0; ni < 4; ni++)
                    MMA3(c[mi][ni], a0, a1, a2, a3, bf[ni][0], bf[ni][1]);
            }
        }
        __syncthreads();
    }

#pragma unroll
    for (int mi = 0; mi < 4; mi++)
#pragma unroll
        for (int ni = 0; ni < 4; ni++) {
            int r1 = r0 + wm * 64 + mi * 16 + g;
            int r2 = r1 + 8;
            int m = mm0 + wn * 32 + ni * 8 + 2 * tg;
            float v0 = c[mi][ni][0] * 0.125f;
            float v1 = c[mi][ni][1] * 0.125f;
            float v2 = c[mi][ni][2] * 0.125f;
            float v3 = c[mi][ni][3] * 0.125f;
            v0 = (m >= 1 && m < r1) ? fmaxf(v0, 0.f) : 0.f;
            v1 = (m + 1 < r1) ? fmaxf(v1, 0.f) : 0.f;
            v2 = (m >= 1 && m < r2) ? fmaxf(v2, 0.f) : 0.f;
            v3 = (m + 1 < r2) ? fmaxf(v3, 0.f) : 0.f;
            *(float2*)&g_F[(size_t)(bb * SEQL + r1) * SEQL + m] = make_float2(v0, v1);
            *(float2*)&g_F[(size_t)(bb * SEQL + r2) * SEQL + m] = make_float2(v2, v3);
        }
}

// ---------------- 3-pass exclusive column scan ----------------
__global__ __launch_bounds__(256) void seg_sum() {
    const int m = blockIdx.x * 256 + threadIdx.x;
    const int seg = blockIdx.y, b = blockIdx.z;
    const float* base = g_F + (size_t)(b * SEQL + seg * SEGROWS) * SEQL + m;
    float s = 0.f;
#pragma unroll 4
    for (int r = 0; r < SEGROWS; r++) s += base[(size_t)r * SEQL];
    g_P[(size_t)(b * NSEG + seg) * SEQL + m] = s;
}

__global__ __launch_bounds__(256) void seg_scan() {
    const int m = blockIdx.x * 256 + threadIdx.x;
    const int b = blockIdx.y;
    float acc = 0.f;
#pragma unroll
    for (int s = 0; s < NSEG; s++) {
        size_t idx = (size_t)(b * NSEG + s) * SEQL + m;
        float v = g_P[idx];
        g_P[idx] = acc;
        acc += v;
    }
}

__global__ __launch_bounds__(256) void final_scan() {
    const int m = blockIdx.x * 256 + threadIdx.x;
    const int seg = blockIdx.y, b = blockIdx.z;
    float acc = g_P[(size_t)(b * NSEG + seg) * SEQL + m];
    float* base = g_F + (size_t)(b * SEQL + seg * SEGROWS) * SEQL + m;
#pragma unroll 4
    for (int r = 0; r < SEGROWS; r++) {
        float c = base[(size_t)r * SEQL];
        base[(size_t)r * SEQL] = acc;
        acc += c;
    }
}

// ---------------- flash attention: QK tf32x1 (pre-truncated), PV bf16x3 -------------
__global__ __launch_bounds__(128) void attn_bf() {
    __shared__ unsigned sKt[64 * 68];
    __shared__ unsigned sVh[64 * 36], sVl[64 * 36];
    const int b = blockIdx.z, h = blockIdx.y;
    const int qt = (int)gridDim.x - 1 - (int)blockIdx.x;
    const int q0 = qt * 64;
    const int tid = threadIdx.x, lane = tid & 31, w = tid >> 5;
    const int g = lane >> 2, tg = lane & 3;

    unsigned qa[8][4];
    const size_t qr1 = (size_t)(b * SEQL + q0 + w * 16 + g) * DMODEL + h * DHEAD;
    const size_t qr2 = qr1 + 8 * DMODEL;
#pragma unroll
    for (int kc = 0; kc < 8; kc++) {
        qa[kc][0] = g_Qt[qr1 + kc * 8 + tg];
        qa[kc][1] = g_Qt[qr2 + kc * 8 + tg];
        qa[kc][2] = g_Qt[qr1 + kc * 8 + tg + 4];
        qa[kc][3] = g_Qt[qr2 + kc * 8 + tg + 4];
    }

    float o[8][4] = {};
    float qm0 = -1e30f, qm1 = -1e30f, lsum0 = 0.f, lsum1 = 0.f;

    for (int kt = 0; kt <= qt; kt++) {
        const int m0 = kt * 64;
#pragma unroll
        for (int t = 0; t < 8; t++) {
            int idx = tid + t * 128;
            int r = idx >> 4, c4 = (idx & 15) * 4;
            *(uint4*)&sKt[r * 68 + c4] =
                *(const uint4*)&g_Kt[(size_t)(b * SEQL + m0 + r) * DMODEL + h * DHEAD + c4];
        }
        const size_t vbase = (size_t)((b * NHEADS + h) * DHEAD) * (SEQL / 2) + (m0 >> 1);
#pragma unroll
        for (int t = 0; t < 4; t++) {
            int idx = tid + t * 128;
            int r = idx >> 3, c4 = (idx & 7) * 4;
            *(uint4*)&sVh[r * 36 + c4] = *(const uint4*)&g_Vth[vbase + (size_t)r * (SEQL / 2) + c4];
            *(uint4*)&sVl[r * 36 + c4] = *(const uint4*)&g_Vtl[vbase + (size_t)r * (SEQL / 2) + c4];
        }
        __syncthreads();

        float sc[8][4] = {};
#pragma unroll
        for (int kc = 0; kc < 8; kc++) {
#pragma unroll
            for (int ni = 0; ni < 8; ni++) {
                unsigned b0 = sKt[(ni * 8 + g) * 68 + kc * 8 + tg];
                unsigned b1 = sKt[(ni * 8 + g) * 68 + kc * 8 + tg + 4];
                MMA(sc[ni], qa[kc][0], qa[kc][1], qa[kc][2], qa[kc][3], b0, b1);
            }
        }

        const bool diag = (kt == qt);
        const int lr1 = w * 16 + g, lr2 = lr1 + 8;
        const size_t frow1 = (size_t)(b * SEQL + q0 + lr1) * SEQL + m0;
        const size_t frow2 = (size_t)(b * SEQL + q0 + lr2) * SEQL + m0;
        float mx0 = -1e30f, mx1 = -1e30f;
#pragma unroll
        for (int ni = 0; ni < 8; ni++) {
            int cl = ni * 8 + 2 * tg;
            float2 f1 = *(const float2*)&g_F[frow1 + cl];
            float2 f2 = *(const float2*)&g_F[frow2 + cl];
            float v0 = sc[ni][0] * 0.125f - f1.x;
            float v1 = sc[ni][1] * 0.125f - f1.y;
            float v2 = sc[ni][2] * 0.125f - f2.x;
            float v3 = sc[ni][3] * 0.125f - f2.y;
            if (diag) {
                if (cl > lr1) v0 = -1e30f;
                if (cl + 1 > lr1) v1 = -1e30f;
                if (cl > lr2) v2 = -1e30f;
                if (cl + 1 > lr2) v3 = -1e30f;
            }
            sc[ni][0] = v0; sc[ni][1] = v1; sc[ni][2] = v2; sc[ni][3] = v3;
            mx0 = fmaxf(mx0, fmaxf(v0, v1));
            mx1 = fmaxf(mx1, fmaxf(v2, v3));
        }
        mx0 = fmaxf(mx0, __shfl_xor_sync(0xffffffffu, mx0, 1));
        mx0 = fmaxf(mx0, __shfl_xor_sync(0xffffffffu, mx0, 2));
        mx1 = fmaxf(mx1, __shfl_xor_sync(0xffffffffu, mx1, 1));
        mx1 = fmaxf(mx1, __shfl_xor_sync(0xffffffffu, mx1, 2));
        const float nm0 = fmaxf(qm0, mx0), nm1 = fmaxf(qm1, mx1);
        const float s0 = __expf(qm0 - nm0), s1 = __expf(qm1 - nm1);
        float ps0 = 0.f, ps1 = 0.f;
#pragma unroll
        for (int ni = 0; ni < 8; ni++) {
            float e0 = __expf(sc[ni][0] - nm0);
            float e1 = __expf(sc[ni][1] - nm0);
            float e2 = __expf(sc[ni][2] - nm1);
            float e3 = __expf(sc[ni][3] - nm1);
            sc[ni][0] = e0; sc[ni][1] = e1; sc[ni][2] = e2; sc[ni][3] = e3;
            ps0 += e0 + e1;
            ps1 += e2 + e3;
            o[ni][0] *= s0; o[ni][1] *= s0; o[ni][2] *= s1; o[ni][3] *= s1;
        }
        ps0 += __shfl_xor_sync(0xffffffffu, ps0, 1);
        ps0 += __shfl_xor_sync(0xffffffffu, ps0, 2);
        ps1 += __shfl_xor_sync(0xffffffffu, ps1, 1);
        ps1 += __shfl_xor_sync(0xffffffffu, ps1, 2);
        lsum0 = lsum0 * s0 + ps0;
        lsum1 = lsum1 * s1 + ps1;
        qm0 = nm0; qm1 = nm1;

#pragma unroll
        for (int kc2 = 0; kc2 < 4; kc2++) {
            unsigned ph0, pl0, ph1, pl1, ph2, pl2, ph3, pl3;
            bsplit(sc[kc2 * 2][0], sc[kc2 * 2][1], ph0, pl0);
            bsplit(sc[kc2 * 2][2], sc[kc2 * 2][3], ph1, pl1);
            bsplit(sc[kc2 * 2 + 1][0], sc[kc2 * 2 + 1][1], ph2, pl2);
            bsplit(sc[kc2 * 2 + 1][2], sc[kc2 * 2 + 1][3], ph3, pl3);
#pragma unroll
            for (int ni = 0; ni < 8; ni++) {
                int vb = (ni * 8 + g) * 36 + kc2 * 8 + tg;
                unsigned vh0 = sVh[vb], vh1 = sVh[vb + 4];
                unsigned vl0 = sVl[vb], vl1 = sVl[vb + 4];
                MMAB(o[ni], ph0, ph1, ph2, ph3, vh0, vh1);
                MMAB(o[ni], ph0, ph1, ph2, ph3, vl0, vl1);
                MMAB(o[ni], pl0, pl1, pl2, pl3, vh0, vh1);
            }
        }
        __syncthreads();
    }

    const float i0 = 1.0f / lsum0, i1 = 1.0f / lsum1;
    const size_t or1 = (size_t)(b * SEQL + q0 + w * 16 + g) * KP + h * 32;
    const size_t or2 = or1 + 8 * KP;
#pragma unroll
    for (int ni = 0; ni < 8; ni++) {
        unsigned hh, ll;
        bsplit(o[ni][0] * i0, o[ni][1] * i0, hh, ll);
        g_Oh[or1 + ni * 4 + tg] = hh;
        g_Ol[or1 + ni * 4 + tg] = ll;
        bsplit(o[ni][2] * i1, o[ni][3] * i1, hh, ll);
        g_Oh[or2 + ni * 4 + tg] = hh;
        g_Ol[or2 + ni * 4 + tg] = ll;
    }
}

// ---------------- launch ----------------
extern "C" void kernel_launch(void* const* d_in, const int* in_sizes, int n_in,
                              void* d_out, int out_size) {
    const float* X  = (const float*)d_in[0];
    const float* Wq = (const float*)d_in[1];
    const float* Wk = (const float*)d_in[2];
    const float* Wv = (const float*)d_in[3];
    const float* Wo = (const float*)d_in[4];
    const float* gq = (const float*)d_in[5];
    const float* bq = (const float*)d_in[6];
    const float* gk = (const float*)d_in[7];
    const float* bk = (const float*)d_in[8];
    float* out = (float*)d_out;

    float *pQ, *pK, *pV;
    unsigned *pQt, *pKt, *pXh, *pXl, *pWvh, *pWvl, *pWoh, *pWol, *pOh, *pOl;
    uint2 *pXt, *pWqkt, *pQhl, *pKhl;
    cudaGetSymbolAddress((void**)&pQ, g_Q);
    cudaGetSymbolAddress((void**)&pK, g_K);
    cudaGetSymbolAddress((void**)&pV, g_V);
    cudaGetSymbolAddress((void**)&pQt, g_Qt);
    cudaGetSymbolAddress((void**)&pKt, g_Kt);
    cudaGetSymbolAddress((void**)&pXt, g_Xt);
    cudaGetSymbolAddress((void**)&pWqkt, g_Wqkt);
    cudaGetSymbolAddress((void**)&pQhl, g_Qhl);
    cudaGetSymbolAddress((void**)&pKhl, g_Khl);
    cudaGetSymbolAddress((void**)&pXh, g_Xh);
    cudaGetSymbolAddress((void**)&pXl, g_Xl);
    cudaGetSymbolAddress((void**)&pWvh, g_Wvh);
    cudaGetSymbolAddress((void**)&pWvl, g_Wvl);
    cudaGetSymbolAddress((void**)&pWoh, g_Woh);
    cudaGetSymbolAddress((void**)&pWol, g_Wol);
    cudaGetSymbolAddress((void**)&pOh, g_Oh);
    cudaGetSymbolAddress((void**)&pOl, g_Ol);

    const int NW = DMODEL * DMODEL;            // 1M weight elements

    // operand pre-splits
    tsplit<<<(MR * DMODEL + 255) / 256, 256>>>(X, pXt, MR * DMODEL);
    tsplit<<<(NW + 255) / 256, 256>>>(Wq, pWqkt, NW);
    tsplit<<<(NW + 255) / 256, 256>>>(Wk, pWqkt + (size_t)NW, NW);
    split_pairs<<<(MR * KP + 255) / 256, 256>>>(X, pXh, pXl, MR * KP);
    split_pairs<<<(NW / 2 + 255) / 256, 256>>>(Wv, pWvh, pWvl, NW / 2);
    split_pairs<<<(NW / 2 + 255) / 256, 256>>>(Wo, pWoh, pWol, NW / 2);

    // fused Q,K projection (tf32x3) + V projection (bf16x3)
    gemm_t3<<<dim3(2 * DMODEL / 128, MR / 128), 256>>>(pXt, pWqkt, pQ, pK,
                                                       MR, DMODEL, DMODEL);
    gemm_bf3<<<dim3(DMODEL / 128, MR / 128), 256>>>(pXh, pXl, pWvh, pWvl, pV,
                                                    MR, DMODEL, KP);

    ln_rows_t<<<MR, 256>>>(pQ, gq, bq, pQt, pQhl);
    ln_rows_t<<<MR, 256>>>(pK, gk, bk, pKt, pKhl);
    vt_split<<<dim3(SEQL / 64, NHEADS, BATCH), 256>>>();

    head0_t3<<<dim3(SEQL / 128, SEQL / 128, BATCH), 256>>>();
    seg_sum<<<dim3(SEQL / 256, NSEG, BATCH), 256>>>();
    seg_scan<<<dim3(SEQL / 256, BATCH), 256>>>();
    final_scan<<<dim3(SEQL / 256, NSEG, BATCH), 256>>>();

    attn_bf<<<dim3(SEQL / 64, NHEADS, BATCH), 128>>>();

    gemm_bf3<<<dim3(DMODEL / 128, MR / 128), 256>>>(pOh, pOl, pWoh, pWol, out,
                                                    MR, DMODEL, KP);
}

// round 6
// speedup vs baseline: 1.1691x; 1.1691x over previous
#include <cuda_runtime.h>
#include <cuda_bf16.h>
#include <math.h>

#define SEQL   2048
#define BATCH  2
#define DMODEL 1024
#define NHEADS 16
#define DHEAD  64
#define MR     (BATCH * SEQL)   // 4096 rows
#define NSEG   16
#define SEGROWS (SEQL / NSEG)   // 128
#define KP     (DMODEL / 2)     // 512 bf16-pair columns

// ---------------- scratch ----------------
__device__ float    g_Q[(size_t)MR * DMODEL];          // f32 (LN'd)
__device__ float    g_K[(size_t)MR * DMODEL];
__device__ float    g_V[(size_t)MR * DMODEL];
__device__ unsigned g_Qt[(size_t)MR * DMODEL];         // tf32 hi bits (for attn QK)
__device__ unsigned g_Kt[(size_t)MR * DMODEL];
__device__ unsigned g_Xh[(size_t)MR * KP];             // bf16 pair splits
__device__ unsigned g_Xl[(size_t)MR * KP];
__device__ unsigned g_Wvh[(size_t)DMODEL * KP];
__device__ unsigned g_Wvl[(size_t)DMODEL * KP];
__device__ unsigned g_Woh[(size_t)DMODEL * KP];
__device__ unsigned g_Wol[(size_t)DMODEL * KP];
__device__ unsigned g_Vth[(size_t)BATCH * NHEADS * DHEAD * (SEQL / 2)];
__device__ unsigned g_Vtl[(size_t)BATCH * NHEADS * DHEAD * (SEQL / 2)];
__device__ unsigned g_Oh[(size_t)MR * KP];
__device__ unsigned g_Ol[(size_t)MR * KP];
__device__ float    g_F[(size_t)BATCH * SEQL * SEQL];
__device__ float    g_P[(size_t)BATCH * NSEG * SEQL];

// ---------------- helpers ----------------
__device__ __forceinline__ unsigned f2t(float x) {
    unsigned r;
    asm("cvt.rna.tf32.f32 %0, %1;" : "=r"(r) : "f"(x));
    return r;
}

__device__ __forceinline__ void bsplit(float x0, float x1, unsigned& h, unsigned& l) {
    asm("cvt.rn.bf16x2.f32 %0, %1, %2;" : "=r"(h) : "f"(x1), "f"(x0));
    __nv_bfloat162 hb = *reinterpret_cast<__nv_bfloat162*>(&h);
    float2 hf = __bfloat1622float2(hb);
    float r0 = x0 - hf.x, r1 = x1 - hf.y;
    asm("cvt.rn.bf16x2.f32 %0, %1, %2;" : "=r"(l) : "f"(r1), "f"(r0));
}

__device__ __forceinline__ void cpa16(void* smem, const void* gmem) {
    unsigned s = (unsigned)__cvta_generic_to_shared(smem);
    asm volatile("cp.async.cg.shared.global [%0], [%1], 16;" :: "r"(s), "l"(gmem));
}
#define CP_COMMIT() asm volatile("cp.async.commit_group;")
#define CP_WAIT1()  asm volatile("cp.async.wait_group 1;")
#define CP_WAIT0()  asm volatile("cp.async.wait_group 0;")

#define MMA(C, A0, A1, A2, A3, B0, B1)                                         \
    asm volatile(                                                              \
        "mma.sync.aligned.m16n8k8.row.col.f32.tf32.tf32.f32 "                  \
        "{%0,%1,%2,%3},{%4,%5,%6,%7},{%8,%9},{%0,%1,%2,%3};"                   \
        : "+f"((C)[0]), "+f"((C)[1]), "+f"((C)[2]), "+f"((C)[3])               \
        : "r"(A0), "r"(A1), "r"(A2), "r"(A3), "r"(B0), "r"(B1))

#define MMAB(C, A0, A1, A2, A3, B0, B1)                                        \
    asm volatile(                                                              \
        "mma.sync.aligned.m16n8k16.row.col.f32.bf16.bf16.f32 "                 \
        "{%0,%1,%2,%3},{%4,%5,%6,%7},{%8,%9},{%0,%1,%2,%3};"                   \
        : "+f"((C)[0]), "+f"((C)[1]), "+f"((C)[2]), "+f"((C)[3])               \
        : "r"(A0), "r"(A1), "r"(A2), "r"(A3), "r"(B0), "r"(B1))

// ---------------- split f32 stream into bf16 hi/lo packed pairs ----------------
__global__ __launch_bounds__(256) void split_pairs(const float* __restrict__ src,
                                                   unsigned* __restrict__ h,
                                                   unsigned* __restrict__ l, int npairs) {
    int i = blockIdx.x * 256 + threadIdx.x;
    if (i < npairs) {
        float2 v = ((const float2*)src)[i];
        unsigned hh, ll;
        bsplit(v.x, v.y, hh, ll);
        h[i] = hh;
        l[i] = ll;
    }
}

// ---------------- fused Q/K projection: tf32x3, cp.async double-buffered ----------
// Y[:, n<1024] -> Q, else K.  Tile 128x128, BK=16, 2 stages.
__global__ __launch_bounds__(256) void gemm_qk(const float* __restrict__ X,
                                               const float* __restrict__ Wq,
                                               const float* __restrict__ Wk,
                                               float* __restrict__ Q,
                                               float* __restrict__ K) {
    __shared__ float As[2][128][20];
    __shared__ float Bs[2][128][20];
    const int tid = threadIdx.x, lane = tid & 31, warp = tid >> 5;
    const int g = lane >> 2, tg = lane & 3;
    const int wm = warp >> 2, wn = warp & 3;
    const int m0 = blockIdx.y * 128, n0 = blockIdx.x * 128;

    const float* Asrc = X + (size_t)m0 * DMODEL;
    const float* Bsrc = (n0 < DMODEL) ? Wq + (size_t)n0 * DMODEL
                                      : Wk + (size_t)(n0 - DMODEL) * DMODEL;

    const int lr = tid >> 2, lc = (tid & 3) * 4;   // 256 threads -> 128 rows x 16 cols (2 passes)

    float c[4][4][4] = {};

    // prefetch stage 0
#pragma unroll
    for (int t = 0; t < 2; t++) {
        int r = lr + t * 64;
        cpa16(&As[0][r][lc], &Asrc[(size_t)r * DMODEL + lc]);
        cpa16(&Bs[0][r][lc], &Bsrc[(size_t)r * DMODEL + lc]);
    }
    CP_COMMIT();

    const int nIt = DMODEL / 16;
    for (int it = 0; it < nIt; it++) {
        const int st = it & 1;
        if (it + 1 < nIt) {
            const int k0 = (it + 1) * 16;
#pragma unroll
            for (int t = 0; t < 2; t++) {
                int r = lr + t * 64;
                cpa16(&As[st ^ 1][r][lc], &Asrc[(size_t)r * DMODEL + k0 + lc]);
                cpa16(&Bs[st ^ 1][r][lc], &Bsrc[(size_t)r * DMODEL + k0 + lc]);
            }
            CP_COMMIT();
            CP_WAIT1();
        } else {
            CP_WAIT0();
        }
        __syncthreads();

#pragma unroll
        for (int kc = 0; kc < 2; kc++) {
            unsigned bh[4][2], bl[4][2];
#pragma unroll
            for (int ni = 0; ni < 4; ni++) {
                int nb = wn * 32 + ni * 8;
                float b0 = Bs[st][nb + g][kc * 8 + tg];
                float b1 = Bs[st][nb + g][kc * 8 + tg + 4];
                bh[ni][0] = f2t(b0);
                bh[ni][1] = f2t(b1);
                bl[ni][0] = f2t(b0 - __uint_as_float(bh[ni][0]));
                bl[ni][1] = f2t(b1 - __uint_as_float(bh[ni][1]));
            }
#pragma unroll
            for (int mi = 0; mi < 4; mi++) {
                int rm = wm * 64 + mi * 16;
                float a0 = As[st][rm + g][kc * 8 + tg];
                float a1 = As[st][rm + g + 8][kc * 8 + tg];
                float a2 = As[st][rm + g][kc * 8 + tg + 4];
                float a3 = As[st][rm + g + 8][kc * 8 + tg + 4];
                unsigned ah0 = f2t(a0), ah1 = f2t(a1), ah2 = f2t(a2), ah3 = f2t(a3);
                unsigned al0 = f2t(a0 - __uint_as_float(ah0));
                unsigned al1 = f2t(a1 - __uint_as_float(ah1));
                unsigned al2 = f2t(a2 - __uint_as_float(ah2));
                unsigned al3 = f2t(a3 - __uint_as_float(ah3));
#pragma unroll
                for (int ni = 0; ni < 4; ni++) {
                    MMA(c[mi][ni], ah0, ah1, ah2, ah3, bh[ni][0], bh[ni][1]);
                    MMA(c[mi][ni], ah0, ah1, ah2, ah3, bl[ni][0], bl[ni][1]);
                    MMA(c[mi][ni], al0, al1, al2, al3, bh[ni][0], bh[ni][1]);
                }
            }
        }
        __syncthreads();
    }

    float* Y = (n0 < DMODEL) ? Q : K;
    const int col0 = (n0 < DMODEL) ? n0 : n0 - DMODEL;
#pragma unroll
    for (int mi = 0; mi < 4; mi++)
#pragma unroll
        for (int ni = 0; ni < 4; ni++) {
            int r = m0 + wm * 64 + mi * 16 + g;
            int col = col0 + wn * 32 + ni * 8 + 2 * tg;
            *(float2*)&Y[(size_t)r * DMODEL + col] = make_float2(c[mi][ni][0], c[mi][ni][1]);
            *(float2*)&Y[(size_t)(r + 8) * DMODEL + col] = make_float2(c[mi][ni][2], c[mi][ni][3]);
        }
}

// ---------------- GEMM bf16 x3, cp.async double-buffered, dynamic smem ----------
// stage layout: [st][Ah|Al|Bh|Bl], each 128 rows x stride 20 u32, BK=16 pairs.
__global__ __launch_bounds__(256) void gemm_bf3(const unsigned* __restrict__ Ah,
                                                const unsigned* __restrict__ Al,
                                                const unsigned* __restrict__ Bh,
                                                const unsigned* __restrict__ Bl,
                                                float* __restrict__ Y,
                                                int M, int N, int Kp) {
    extern __shared__ unsigned dsm[];
    const int AS = 128 * 20;                 // per-array u32 stride
    const int tid = threadIdx.x, lane = tid & 31, warp = tid >> 5;
    const int g = lane >> 2, tg = lane & 3;
    const int wm = warp >> 2, wn = warp & 3;
    const int m0 = blockIdx.y * 128, n0 = blockIdx.x * 128;

    const int lr = tid >> 2, lc = (tid & 3) * 4;

    float c[4][4][4] = {};

    // prefetch stage 0
    {
        unsigned* base = dsm;
#pragma unroll
        for (int t = 0; t < 2; t++) {
            int r = lr + t * 64;
            cpa16(&base[0 * AS + r * 20 + lc], &Ah[(size_t)(m0 + r) * Kp + lc]);
            cpa16(&base[1 * AS + r * 20 + lc], &Al[(size_t)(m0 + r) * Kp + lc]);
            cpa16(&base[2 * AS + r * 20 + lc], &Bh[(size_t)(n0 + r) * Kp + lc]);
            cpa16(&base[3 * AS + r * 20 + lc], &Bl[(size_t)(n0 + r) * Kp + lc]);
        }
        CP_COMMIT();
    }

    const int nIt = Kp / 16;
    for (int it = 0; it < nIt; it++) {
        const int st = it & 1;
        if (it + 1 < nIt) {
            const int k0 = (it + 1) * 16;
            unsigned* base = dsm + (st ^ 1) * 4 * AS;
#pragma unroll
            for (int t = 0; t < 2; t++) {
                int r = lr + t * 64;
                cpa16(&base[0 * AS + r * 20 + lc], &Ah[(size_t)(m0 + r) * Kp + k0 + lc]);
                cpa16(&base[1 * AS + r * 20 + lc], &Al[(size_t)(m0 + r) * Kp + k0 + lc]);
                cpa16(&base[2 * AS + r * 20 + lc], &Bh[(size_t)(n0 + r) * Kp + k0 + lc]);
                cpa16(&base[3 * AS + r * 20 + lc], &Bl[(size_t)(n0 + r) * Kp + k0 + lc]);
            }
            CP_COMMIT();
            CP_WAIT1();
        } else {
            CP_WAIT0();
        }
        __syncthreads();

        unsigned* sAh = dsm + st * 4 * AS;
        unsigned* sAl = sAh + AS;
        unsigned* sBh = sAh + 2 * AS;
        unsigned* sBl = sAh + 3 * AS;
#pragma unroll
        for (int kc = 0; kc < 2; kc++) {
            unsigned bhf[4][2], blf[4][2];
#pragma unroll
            for (int ni = 0; ni < 4; ni++) {
                int nb = (wn * 32 + ni * 8 + g) * 20 + kc * 8 + tg;
                bhf[ni][0] = sBh[nb];
                bhf[ni][1] = sBh[nb + 4];
                blf[ni][0] = sBl[nb];
                blf[ni][1] = sBl[nb + 4];
            }
#pragma unroll
            for (int mi = 0; mi < 4; mi++) {
                int r1 = (wm * 64 + mi * 16 + g) * 20 + kc * 8 + tg;
                int r2 = r1 + 8 * 20;
                unsigned ah0 = sAh[r1], ah1 = sAh[r2], ah2 = sAh[r1 + 4], ah3 = sAh[r2 + 4];
                unsigned al0 = sAl[r1], al1 = sAl[r2], al2 = sAl[r1 + 4], al3 = sAl[r2 + 4];
#pragma unroll
                for (int ni = 0; ni < 4; ni++) {
                    MMAB(c[mi][ni], ah0, ah1, ah2, ah3, bhf[ni][0], bhf[ni][1]);
                    MMAB(c[mi][ni], ah0, ah1, ah2, ah3, blf[ni][0], blf[ni][1]);
                    MMAB(c[mi][ni], al0, al1, al2, al3, bhf[ni][0], bhf[ni][1]);
                }
            }
        }
        __syncthreads();
    }

#pragma unroll
    for (int mi = 0; mi < 4; mi++)
#pragma unroll
        for (int ni = 0; ni < 4; ni++) {
            int r = m0 + wm * 64 + mi * 16 + g;
            int col = n0 + wn * 32 + ni * 8 + 2 * tg;
            *(float2*)&Y[(size_t)r * N + col] = make_float2(c[mi][ni][0], c[mi][ni][1]);
            *(float2*)&Y[(size_t)(r + 8) * N + col] = make_float2(c[mi][ni][2], c[mi][ni][3]);
        }
}

// ---------------- row LayerNorm (in place) + tf32-truncated copy ----------------
__global__ __launch_bounds__(256) void ln_rows_t(float* __restrict__ Y,
                                                 const float* __restrict__ g,
                                                 const float* __restrict__ b,
                                                 unsigned* __restrict__ T) {
    const int row = blockIdx.x;
    float* y = Y + (size_t)row * DMODEL;
    unsigned* t = T + (size_t)row * DMODEL;
    __shared__ float red[256];

    float s = 0.f;
    for (int i = threadIdx.x; i < DMODEL; i += 256) s += y[i];
    red[threadIdx.x] = s;
    __syncthreads();
    for (int o = 128; o > 0; o >>= 1) {
        if (threadIdx.x < o) red[threadIdx.x] += red[threadIdx.x + o];
        __syncthreads();
    }
    const float mu = red[0] * (1.0f / DMODEL);
    __syncthreads();

    float v = 0.f;
    for (int i = threadIdx.x; i < DMODEL; i += 256) {
        float d = y[i] - mu;
        v += d * d;
    }
    red[threadIdx.x] = v;
    __syncthreads();
    for (int o = 128; o > 0; o >>= 1) {
        if (threadIdx.x < o) red[threadIdx.x] += red[threadIdx.x + o];
        __syncthreads();
    }
    const float rstd = rsqrtf(red[0] * (1.0f / DMODEL) + 1e-5f);
    __syncthreads();

    for (int i = threadIdx.x; i < DMODEL; i += 256) {
        float val = (y[i] - mu) * rstd * g[i] + b[i];
        y[i] = val;
        t[i] = f2t(val);
    }
}

// ---------------- V transpose + bf16 split ----------------
__global__ __launch_bounds__(256) void vt_split() {
    __shared__ float tile[64][68];
    const int b = blockIdx.z, h = blockIdx.y, n0 = blockIdx.x * 64;
    const int tid = threadIdx.x;
#pragma unroll
    for (int t = 0; t < 4; t++) {
        int idx = tid + t * 256;
        int r = idx >> 4, c4 = (idx & 15) * 4;
        *(float4*)&tile[r][c4] =
            *(const float4*)&g_V[(size_t)(b * SEQL + n0 + r) * DMODEL + h * DHEAD + c4];
    }
    __syncthreads();
#pragma unroll
    for (int t = 0; t < 8; t++) {
        int idx = tid + t * 256;
        int d = idx >> 5, j = idx & 31;
        unsigned hh, ll;
        bsplit(tile[2 * j][d], tile[2 * j + 1][d], hh, ll);
        size_t off = ((size_t)((b * NHEADS + h) * DHEAD + d)) * (SEQL / 2) + (n0 >> 1) + j;
        g_Vth[off] = hh;
        g_Vtl[off] = ll;
    }
}

// ---------------- head-0 scores via tf32 x3 (with upper-tri early exit) ----------------
__global__ __launch_bounds__(256) void head0_tc() {
    const int tid = threadIdx.x, lane = tid & 31, warp = tid >> 5;
    const int g = lane >> 2, tg = lane & 3;
    const int wm = warp >> 2, wn = warp & 3;
    const int bb = blockIdx.z;
    const int r0 = blockIdx.y * 128, mm0 = blockIdx.x * 128;

    if (mm0 >= r0 + 128) {   // tile strictly above diagonal -> exact zeros
        const float2 z = make_float2(0.f, 0.f);
#pragma unroll
        for (int mi = 0; mi < 4; mi++)
#pragma unroll
            for (int ni = 0; ni < 4; ni++) {
                int r1 = r0 + wm * 64 + mi * 16 + g;
                int m = mm0 + wn * 32 + ni * 8 + 2 * tg;
                *(float2*)&g_F[(size_t)(bb * SEQL + r1) * SEQL + m] = z;
                *(float2*)&g_F[(size_t)(bb * SEQL + r1 + 8) * SEQL + m] = z;
            }
        return;
    }

    __shared__ float As[128][36];
    __shared__ float Bs[128][36];
    const float* Aq = g_Q + (size_t)(bb * SEQL + r0) * DMODEL;
    const float* Bk = g_K + (size_t)(bb * SEQL + mm0) * DMODEL;
    const int lrow = tid >> 3, lcol = (tid & 7) * 4;

    float c[4][4][4] = {};

    for (int k0 = 0; k0 < 64; k0 += 32) {
#pragma unroll
        for (int it = 0; it < 4; it++) {
            int r = lrow + it * 32;
            *(float4*)&As[r][lcol] = *(const float4*)&Aq[(size_t)r * DMODEL + k0 + lcol];
            *(float4*)&Bs[r][lcol] = *(const float4*)&Bk[(size_t)r * DMODEL + k0 + lcol];
        }
        __syncthreads();
#pragma unroll
        for (int kc = 0; kc < 4; kc++) {
            unsigned bh[4][2], bl[4][2];
#pragma unroll
            for (int ni = 0; ni < 4; ni++) {
                int nb = wn * 32 + ni * 8;
                float b0 = Bs[nb + g][kc * 8 + tg];
                float b1 = Bs[nb + g][kc * 8 + tg + 4];
                bh[ni][0] = f2t(b0);
                bh[ni][1] = f2t(b1);
                bl[ni][0] = f2t(b0 - __uint_as_float(bh[ni][0]));
                bl[ni][1] = f2t(b1 - __uint_as_float(bh[ni][1]));
            }
#pragma unroll
            for (int mi = 0; mi < 4; mi++) {
                int rm = wm * 64 + mi * 16;
                float a0 = As[rm + g][kc * 8 + tg];
                float a1 = As[rm + g + 8][kc * 8 + tg];
                float a2 = As[rm + g][kc * 8 + tg + 4];
                float a3 = As[rm + g + 8][kc * 8 + tg + 4];
                unsigned ah0 = f2t(a0), ah1 = f2t(a1), ah2 = f2t(a2), ah3 = f2t(a3);
                unsigned al0 = f2t(a0 - __uint_as_float(ah0));
                unsigned al1 = f2t(a1 - __uint_as_float(ah1));
                unsigned al2 = f2t(a2 - __uint_as_float(ah2));
                unsigned al3 = f2t(a3 - __uint_as_float(ah3));
#pragma unroll
                for (int ni = 0; ni < 4; ni++) {
                    MMA(c[mi][ni], ah0, ah1, ah2, ah3, bh[ni][0], bh[ni][1]);
                    MMA(c[mi][ni], ah0, ah1, ah2, ah3, bl[ni][0], bl[ni][1]);
                    MMA(c[mi][ni], al0, al1, al2, al3, bh[ni][0], bh[ni][1]);
                }
            }
        }
        __syncthreads();
    }

#pragma unroll
    for (int mi = 0; mi < 4; mi++)
#pragma unroll
        for (int ni = 0; ni < 4; ni++) {
            int r1 = r0 + wm * 64 + mi * 16 + g;
            int r2 = r1 + 8;
            int m = mm0 + wn * 32 + ni * 8 + 2 * tg;
            float v0 = c[mi][ni][0] * 0.125f;
            float v1 = c[mi][ni][1] * 0.125f;
            float v2 = c[mi][ni][2] * 0.125f;
            float v3 = c[mi][ni][3] * 0.125f;
            v0 = (m >= 1 && m < r1) ? fmaxf(v0, 0.f) : 0.f;
            v1 = (m + 1 < r1) ? fmaxf(v1, 0.f) : 0.f;
            v2 = (m >= 1 && m < r2) ? fmaxf(v2, 0.f) : 0.f;
            v3 = (m + 1 < r2) ? fmaxf(v3, 0.f) : 0.f;
            *(float2*)&g_F[(size_t)(bb * SEQL + r1) * SEQL + m] = make_float2(v0, v1);
            *(float2*)&g_F[(size_t)(bb * SEQL + r2) * SEQL + m] = make_float2(v2, v3);
        }
}

// ---------------- 3-pass exclusive column scan ----------------
__global__ __launch_bounds__(256) void seg_sum() {
    const int m = blockIdx.x * 256 + threadIdx.x;
    const int seg = blockIdx.y, b = blockIdx.z;
    const float* base = g_F + (size_t)(b * SEQL + seg * SEGROWS) * SEQL + m;
    float s = 0.f;
#pragma unroll 4
    for (int r = 0; r < SEGROWS; r++) s += base[(size_t)r * SEQL];
    g_P[(size_t)(b * NSEG + seg) * SEQL + m] = s;
}

__global__ __launch_bounds__(256) void seg_scan() {
    const int m = blockIdx.x * 256 + threadIdx.x;
    const int b = blockIdx.y;
    float acc = 0.f;
#pragma unroll
    for (int s = 0; s < NSEG; s++) {
        size_t idx = (size_t)(b * NSEG + s) * SEQL + m;
        float v = g_P[idx];
        g_P[idx] = acc;
        acc += v;
    }
}

__global__ __launch_bounds__(256) void final_scan() {
    const int m = blockIdx.x * 256 + threadIdx.x;
    const int seg = blockIdx.y, b = blockIdx.z;
    float acc = g_P[(size_t)(b * NSEG + seg) * SEQL + m];
    float* base = g_F + (size_t)(b * SEQL + seg * SEGROWS) * SEQL + m;
#pragma unroll 4
    for (int r = 0; r < SEGROWS; r++) {
        float c = base[(size_t)r * SEQL];
        base[(size_t)r * SEQL] = acc;
        acc += c;
    }
}

// ---------------- flash attention: QK tf32x1 (pre-truncated), PV bf16x3 -------------
__global__ __launch_bounds__(128) void attn_bf() {
    __shared__ unsigned sKt[64 * 68];
    __shared__ unsigned sVh[64 * 36], sVl[64 * 36];
    const int b = blockIdx.z, h = blockIdx.y;
    const int qt = (int)gridDim.x - 1 - (int)blockIdx.x;
    const int q0 = qt * 64;
    const int tid = threadIdx.x, lane = tid & 31, w = tid >> 5;
    const int g = lane >> 2, tg = lane & 3;

    unsigned qa[8][4];
    const size_t qr1 = (size_t)(b * SEQL + q0 + w * 16 + g) * DMODEL + h * DHEAD;
    const size_t qr2 = qr1 + 8 * DMODEL;
#pragma unroll
    for (int kc = 0; kc < 8; kc++) {
        qa[kc][0] = g_Qt[qr1 + kc * 8 + tg];
        qa[kc][1] = g_Qt[qr2 + kc * 8 + tg];
        qa[kc][2] = g_Qt[qr1 + kc * 8 + tg + 4];
        qa[kc][3] = g_Qt[qr2 + kc * 8 + tg + 4];
    }

    float o[8][4] = {};
    float qm0 = -1e30f, qm1 = -1e30f, lsum0 = 0.f, lsum1 = 0.f;

    for (int kt = 0; kt <= qt; kt++) {
        const int m0 = kt * 64;
#pragma unroll
        for (int t = 0; t < 8; t++) {
            int idx = tid + t * 128;
            int r = idx >> 4, c4 = (idx & 15) * 4;
            *(uint4*)&sKt[r * 68 + c4] =
                *(const uint4*)&g_Kt[(size_t)(b * SEQL + m0 + r) * DMODEL + h * DHEAD + c4];
        }
        const size_t vbase = (size_t)((b * NHEADS + h) * DHEAD) * (SEQL / 2) + (m0 >> 1);
#pragma unroll
        for (int t = 0; t < 4; t++) {
            int idx = tid + t * 128;
            int r = idx >> 3, c4 = (idx & 7) * 4;
            *(uint4*)&sVh[r * 36 + c4] = *(const uint4*)&g_Vth[vbase + (size_t)r * (SEQL / 2) + c4];
            *(uint4*)&sVl[r * 36 + c4] = *(const uint4*)&g_Vtl[vbase + (size_t)r * (SEQL / 2) + c4];
        }
        __syncthreads();

        float sc[8][4] = {};
#pragma unroll
        for (int kc = 0; kc < 8; kc++) {
#pragma unroll
            for (int ni = 0; ni < 8; ni++) {
                unsigned b0 = sKt[(ni * 8 + g) * 68 + kc * 8 + tg];
                unsigned b1 = sKt[(ni * 8 + g) * 68 + kc * 8 + tg + 4];
                MMA(sc[ni], qa[kc][0], qa[kc][1], qa[kc][2], qa[kc][3], b0, b1);
            }
        }

        const bool diag = (kt == qt);
        const int lr1 = w * 16 + g, lr2 = lr1 + 8;
        const size_t frow1 = (size_t)(b * SEQL + q0 + lr1) * SEQL + m0;
        const size_t frow2 = (size_t)(b * SEQL + q0 + lr2) * SEQL + m0;
        float mx0 = -1e30f, mx1 = -1e30f;
#pragma unroll
        for (int ni = 0; ni < 8; ni++) {
            int cl = ni * 8 + 2 * tg;
            float2 f1 = *(const float2*)&g_F[frow1 + cl];
            float2 f2 = *(const float2*)&g_F[frow2 + cl];
            float v0 = sc[ni][0] * 0.125f - f1.x;
            float v1 = sc[ni][1] * 0.125f - f1.y;
            float v2 = sc[ni][2] * 0.125f - f2.x;
            float v3 = sc[ni][3] * 0.125f - f2.y;
            if (diag) {
                if (cl > lr1) v0 = -1e30f;
                if (cl + 1 > lr1) v1 = -1e30f;
                if (cl > lr2) v2 = -1e30f;
                if (cl + 1 > lr2) v3 = -1e30f;
            }
            sc[ni][0] = v0; sc[ni][1] = v1; sc[ni][2] = v2; sc[ni][3] = v3;
            mx0 = fmaxf(mx0, fmaxf(v0, v1));
            mx1 = fmaxf(mx1, fmaxf(v2, v3));
        }
        mx0 = fmaxf(mx0, __shfl_xor_sync(0xffffffffu, mx0, 1));
        mx0 = fmaxf(mx0, __shfl_xor_sync(0xffffffffu, mx0, 2));
        mx1 = fmaxf(mx1, __shfl_xor_sync(0xffffffffu, mx1, 1));
        mx1 = fmaxf(mx1, __shfl_xor_sync(0xffffffffu, mx1, 2));
        const float nm0 = fmaxf(qm0, mx0), nm1 = fmaxf(qm1, mx1);
        const float s0 = __expf(qm0 - nm0), s1 = __expf(qm1 - nm1);
        float ps0 = 0.f, ps1 = 0.f;
#pragma unroll
        for (int ni = 0; ni < 8; ni++) {
            float e0 = __expf(sc[ni][0] - nm0);
            float e1 = __expf(sc[ni][1] - nm0);
            float e2 = __expf(sc[ni][2] - nm1);
            float e3 = __expf(sc[ni][3] - nm1);
            sc[ni][0] = e0; sc[ni][1] = e1; sc[ni][2] = e2; sc[ni][3] = e3;
            ps0 += e0 + e1;
            ps1 += e2 + e3;
            o[ni][0] *= s0; o[ni][1] *= s0; o[ni][2] *= s1; o[ni][3] *= s1;
        }
        ps0 += __shfl_xor_sync(0xffffffffu, ps0, 1);
        ps0 += __shfl_xor_sync(0xffffffffu, ps0, 2);
        ps1 += __shfl_xor_sync(0xffffffffu, ps1, 1);
        ps1 += __shfl_xor_sync(0xffffffffu, ps1, 2);
        lsum0 = lsum0 * s0 + ps0;
        lsum1 = lsum1 * s1 + ps1;
        qm0 = nm0; qm1 = nm1;

#pragma unroll
        for (int kc2 = 0; kc2 < 4; kc2++) {
            unsigned ph0, pl0, ph1, pl1, ph2, pl2, ph3, pl3;
            bsplit(sc[kc2 * 2][0], sc[kc2 * 2][1], ph0, pl0);
            bsplit(sc[kc2 * 2][2], sc[kc2 * 2][3], ph1, pl1);
            bsplit(sc[kc2 * 2 + 1][0], sc[kc2 * 2 + 1][1], ph2, pl2);
            bsplit(sc[kc2 * 2 + 1][2], sc[kc2 * 2 + 1][3], ph3, pl3);
#pragma unroll
            for (int ni = 0; ni < 8; ni++) {
                int vb = (ni * 8 + g) * 36 + kc2 * 8 + tg;
                unsigned vh0 = sVh[vb], vh1 = sVh[vb + 4];
                unsigned vl0 = sVl[vb], vl1 = sVl[vb + 4];
                MMAB(o[ni], ph0, ph1, ph2, ph3, vh0, vh1);
                MMAB(o[ni], ph0, ph1, ph2, ph3, vl0, vl1);
                MMAB(o[ni], pl0, pl1, pl2, pl3, vh0, vh1);
            }
        }
        __syncthreads();
    }

    const float i0 = 1.0f / lsum0, i1 = 1.0f / lsum1;
    const size_t or1 = (size_t)(b * SEQL + q0 + w * 16 + g) * KP + h * 32;
    const size_t or2 = or1 + 8 * KP;
#pragma unroll
    for (int ni = 0; ni < 8; ni++) {
        unsigned hh, ll;
        bsplit(o[ni][0] * i0, o[ni][1] * i0, hh, ll);
        g_Oh[or1 + ni * 4 + tg] = hh;
        g_Ol[or1 + ni * 4 + tg] = ll;
        bsplit(o[ni][2] * i1, o[ni][3] * i1, hh, ll);
        g_Oh[or2 + ni * 4 + tg] = hh;
        g_Ol[or2 + ni * 4 + tg] = ll;
    }
}

// ---------------- launch ----------------
extern "C" void kernel_launch(void* const* d_in, const int* in_sizes, int n_in,
                              void* d_out, int out_size) {
    const float* X  = (const float*)d_in[0];
    const float* Wq = (const float*)d_in[1];
    const float* Wk = (const float*)d_in[2];
    const float* Wv = (const float*)d_in[3];
    const float* Wo = (const float*)d_in[4];
    const float* gq = (const float*)d_in[5];
    const float* bq = (const float*)d_in[6];
    const float* gk = (const float*)d_in[7];
    const float* bk = (const float*)d_in[8];
    float* out = (float*)d_out;

    float *pQ, *pK, *pV;
    unsigned *pQt, *pKt, *pXh, *pXl, *pWvh, *pWvl, *pWoh, *pWol, *pOh, *pOl;
    cudaGetSymbolAddress((void**)&pQ, g_Q);
    cudaGetSymbolAddress((void**)&pK, g_K);
    cudaGetSymbolAddress((void**)&pV, g_V);
    cudaGetSymbolAddress((void**)&pQt, g_Qt);
    cudaGetSymbolAddress((void**)&pKt, g_Kt);
    cudaGetSymbolAddress((void**)&pXh, g_Xh);
    cudaGetSymbolAddress((void**)&pXl, g_Xl);
    cudaGetSymbolAddress((void**)&pWvh, g_Wvh);
    cudaGetSymbolAddress((void**)&pWvl, g_Wvl);
    cudaGetSymbolAddress((void**)&pWoh, g_Woh);
    cudaGetSymbolAddress((void**)&pWol, g_Wol);
    cudaGetSymbolAddress((void**)&pOh, g_Oh);
    cudaGetSymbolAddress((void**)&pOl, g_Ol);

    const int NW = DMODEL * DMODEL;
    const int BF3_SMEM = 2 * 4 * 128 * 20 * 4;   // 81920 bytes
    cudaFuncSetAttribute(gemm_bf3, cudaFuncAttributeMaxDynamicSharedMemorySize, BF3_SMEM);

    // operand pre-splits (bf16 path only; tf32 path stages f32 directly)
    split_pairs<<<(MR * KP + 255) / 256, 256>>>(X, pXh, pXl, MR * KP);
    split_pairs<<<(NW / 2 + 255) / 256, 256>>>(Wv, pWvh, pWvl, NW / 2);
    split_pairs<<<(NW / 2 + 255) / 256, 256>>>(Wo, pWoh, pWol, NW / 2);

    // fused Q,K projection (tf32x3, double-buffered) + V projection (bf16x3)
    gemm_qk<<<dim3(2 * DMODEL / 128, MR / 128), 256>>>(X, Wq, Wk, pQ, pK);
    gemm_bf3<<<dim3(DMODEL / 128, MR / 128), 256, BF3_SMEM>>>(pXh, pXl, pWvh, pWvl, pV,
                                                              MR, DMODEL, KP);

    ln_rows_t<<<MR, 256>>>(pQ, gq, bq, pQt);
    ln_rows_t<<<MR, 256>>>(pK, gk, bk, pKt);
    vt_split<<<dim3(SEQL / 64, NHEADS, BATCH), 256>>>();

    head0_tc<<<dim3(SEQL / 128, SEQL / 128, BATCH), 256>>>();
    seg_sum<<<dim3(SEQL / 256, NSEG, BATCH), 256>>>();
    seg_scan<<<dim3(SEQL / 256, BATCH), 256>>>();
    final_scan<<<dim3(SEQL / 256, NSEG, BATCH), 256>>>();

    attn_bf<<<dim3(SEQL / 64, NHEADS, BATCH), 128>>>();

    gemm_bf3<<<dim3(DMODEL / 128, MR / 128), 256, BF3_SMEM>>>(pOh, pOl, pWoh, pWol, out,
                                                              MR, DMODEL, KP);
}